// round 10
// baseline (speedup 1.0000x reference)
#include <cuda_runtime.h>
#include <math.h>
#include <stdint.h>

#define N_MAX 10000
#define E_MAX 100000

// Scratch (no cudaMalloc allowed)
__device__ float g_q[N_MAX * 20];
__device__ float g_z[N_MAX];
__device__ float g_ex[E_MAX];
__device__ float g_v[(size_t)E_MAX * 40];
__device__ uint32_t g_bk[32 * 328];   // W2k tf32 bits, [k][n] pitch 328
__device__ uint32_t g_bv[32 * 648];   // W2v tf32 bits, [k][n] pitch 648

__device__ __forceinline__ uint32_t cvt_tf32(float x) {
    uint32_t r; asm("cvt.rna.tf32.f32 %0, %1;" : "=r"(r) : "f"(x)); return r;
}
__device__ __forceinline__ float dot4(float4 a, float4 b) {
    return a.x * b.x + a.y * b.y + a.z * b.z + a.w * b.w;
}

// ---------------------------------------------------------------------------
// Prep: convert W2 to tf32 bit layout with conflict-free pitches
// ---------------------------------------------------------------------------
__global__ void k_prep(const float* __restrict__ fck_w2, const float* __restrict__ fcv_w2)
{
    int idx = blockIdx.x * blockDim.x + threadIdx.x;
    if (idx < 32 * 328) {
        int k = idx / 328, n = idx % 328;
        g_bk[idx] = (n < 320) ? cvt_tf32(fck_w2[k * 320 + n]) : 0u;
    }
    idx -= 32 * 328;
    if (idx >= 0 && idx < 32 * 648) {
        int k = idx / 648, n = idx % 648;
        g_bv[idx] = (n < 640) ? cvt_tf32(fcv_w2[k * 640 + n]) : 0u;
    }
}

// ---------------------------------------------------------------------------
// Kernel 0: per-node q projection, zero z and out
// ---------------------------------------------------------------------------
__global__ void __launch_bounds__(64) k_nodes(const float* __restrict__ node_ft,
                        const float* __restrict__ wqs, const float* __restrict__ wqv,
                        float* __restrict__ out, int N)
{
    int n = blockIdx.x * blockDim.x + threadIdx.x;
    if (n >= N) return;
    const float* x = node_ft + (size_t)n * 40;
    float xs[16], xv[24];
#pragma unroll
    for (int i = 0; i < 16; i++) xs[i] = x[i];
#pragma unroll
    for (int i = 0; i < 24; i++) xv[i] = x[16 + i];
    const float s0 = 0.25f, s1 = 0.35355339059327373f;
    float q[20];
#pragma unroll
    for (int o = 0; o < 8; o++) {
        float a = 0.f;
#pragma unroll
        for (int i = 0; i < 16; i++) a += xs[i] * wqs[i * 8 + o];
        q[o] = a * s0;
    }
#pragma unroll
    for (int o = 0; o < 4; o++)
#pragma unroll
        for (int c = 0; c < 3; c++) {
            float a = 0.f;
#pragma unroll
            for (int i = 0; i < 8; i++) a += xv[i * 3 + c] * wqv[i * 4 + o];
            q[8 + o * 3 + c] = a * s1;
        }
#pragma unroll
    for (int i = 0; i < 20; i++) g_q[(size_t)n * 20 + i] = q[i];
    g_z[n] = 0.f;
    float4 z4 = make_float4(0.f, 0.f, 0.f, 0.f);
#pragma unroll
    for (int i = 0; i < 10; i++)
        *reinterpret_cast<float4*>(&out[(size_t)n * 40 + i * 4]) = z4;
}

// ---------------------------------------------------------------------------
// Main kernel: persistent, 16 edges/tile, mma.sync tf32 weight-gen,
// TRANSPOSED per-path weight layout ([o][i]) for vectorized LDS.128 epilogue.
//
// W tile layout per edge (968 floats):
//   k: w1T[8][16]@0  w2T[8][8]@128  w3T[4][16]@192 w4T[4][8]@256 w5T[4][8]@288
//   v: w1T[16][16]@320 w2T[16][8]@576 w3T[8][16]@704 w4T[8][8]@832 w5T[8][8]@896
// P layout per edge (96 floats):
//   XS@0(16) XVt@16([c][8]) SHS@40 SHV@41(3) PSS@44(16) PVV@60(8) PXXt@68([c][8])
// ---------------------------------------------------------------------------
#define SB_BK   0          // 32 x 328 (tf32 bits)
#define SB_BV   10496      // 32 x 648
#define SB_W    31232      // 16 x 968
#define SB_HK   46720      // 16 x 33 (tf32 bits)
#define SB_HV   47248      // 16 x 33
#define SB_W1K  47776      // 512
#define SB_W1V  48288      // 512
#define SB_WDS  48800      // 64
#define SB_WDV  48864      // 16
#define SB_ES   48880      // 16 x 16
#define SB_SH   49136      // 16 x 4
#define SB_IX   49200      // 32 ints
#define SB_P    49232      // 16 x 96
#define SB_K    50768      // 16 x 20
#define SB_PERM 51088      // 960 uint16 = 480 floats
#define SMEM_FLOATS 51568
#define SMEM_BYTES (SMEM_FLOATS * 4)
#define WP 968

__global__ void __launch_bounds__(512, 1) k_edges(
    const float* __restrict__ node_ft,
    const int* __restrict__ eidx,
    const float* __restrict__ edge_sh,
    const float* __restrict__ edge_sc,
    const float* __restrict__ fck_w1,
    const float* __restrict__ fcv_w1,
    const float* __restrict__ wdot_s,
    const float* __restrict__ wdot_v,
    int E)
{
    extern __shared__ float sm[];
    const int tid  = threadIdx.x;
    const int wid  = tid >> 5;
    const int lane = tid & 31;

    // ---- startup: stage B (tf32 W2), W1, wdot, build perm LUT ----
    {
        uint32_t* bk = (uint32_t*)(sm + SB_BK);
        uint32_t* bv = (uint32_t*)(sm + SB_BV);
        for (int i = tid; i < 32 * 328; i += 512) bk[i] = g_bk[i];
        for (int i = tid; i < 32 * 648; i += 512) bv[i] = g_bv[i];
        if (tid < 512) sm[SB_W1K + tid] = fck_w1[tid];
        for (int i = tid; i < 512; i += 512) sm[SB_W1V + i] = fcv_w1[i];
        if (tid < 64) sm[SB_WDS + tid] = wdot_s[tid];
        if (tid < 16) sm[SB_WDV + tid] = wdot_v[tid];

        // perm LUT: original flattened column -> transposed position
        uint16_t* perm = (uint16_t*)(sm + SB_PERM);
        for (int col = tid; col < 960; col += 512) {
            int p;
            if (col < 320) {                        // k-branch
                if      (col < 128) { int c0 = col;       p = 0   + (c0 % 8)  * 16 + c0 / 8;  }
                else if (col < 192) { int c0 = col - 128; p = 128 + (c0 % 8)  * 8  + c0 / 8;  }
                else if (col < 256) { int c0 = col - 192; p = 192 + (c0 % 4)  * 16 + c0 / 4;  }
                else if (col < 288) { int c0 = col - 256; p = 256 + (c0 % 4)  * 8  + c0 / 4;  }
                else                { int c0 = col - 288; p = 288 + (c0 % 4)  * 8  + c0 / 4;  }
            } else {                                // v-branch
                int cv = col - 320;
                if      (cv < 256) { p = 320 + (cv % 16) * 16 + cv / 16; }
                else if (cv < 384) { int c0 = cv - 256; p = 576 + (c0 % 16) * 8  + c0 / 16; }
                else if (cv < 512) { int c0 = cv - 384; p = 704 + (c0 % 8)  * 16 + c0 / 8;  }
                else if (cv < 576) { int c0 = cv - 512; p = 832 + (c0 % 8)  * 8  + c0 / 8;  }
                else               { int c0 = cv - 576; p = 896 + (c0 % 8)  * 8  + c0 / 8;  }
            }
            perm[col] = (uint16_t)p;
        }
    }
    __syncthreads();

    const float ISQ32 = 0.17677669529663687f;
    const float ISQ24 = 0.2041241452319315f;
    const float ISQ3  = 0.5773502691896258f;
    const float ISQ2  = 0.7071067811865476f;

    int* ixs = (int*)(sm + SB_IX);
    int* ixr = (int*)(sm + SB_IX + 16);
    const uint16_t* perm = (const uint16_t*)(sm + SB_PERM);
    const int ntiles = (E + 15) >> 4;

    for (int t = blockIdx.x; t < ntiles; t += 148) {
        const int ebase = t << 4;

        // ---- stage edge data ----
        if (tid < 256) {
            int e = tid >> 4, i = tid & 15;
            int eg = min(ebase + e, E - 1);
            sm[SB_ES + tid] = edge_sc[(size_t)eg * 16 + i];
        } else if (tid < 288) {
            int f = tid - 256;
            int e = f & 15;
            int eg = min(ebase + e, E - 1);
            if (f < 16) ixs[e] = eidx[eg];
            else        ixr[e] = eidx[E + eg];
        } else if (tid < 352) {
            int f = tid - 288;
            int eg = min(ebase + (f >> 2), E - 1);
            sm[SB_SH + f] = edge_sh[(size_t)eg * 4 + (f & 3)];
        }
        __syncthreads();

        // ---- P1: hidden activations -> tf32 bits in HK/HV ----
        uint32_t* HK = (uint32_t*)(sm + SB_HK);
        uint32_t* HV = (uint32_t*)(sm + SB_HV);
#pragma unroll
        for (int s = 0; s < 2; s++) {
            int task = tid + s * 512;
            int e = task >> 6, jj = task & 63, j = jj & 31;
            const float* W1 = sm + ((jj < 32) ? SB_W1K : SB_W1V);
            const float* es = sm + SB_ES + e * 16;
            float a = 0.f;
#pragma unroll
            for (int i = 0; i < 16; i++) a += es[i] * W1[i * 32 + j];
            a *= 0.25f;
            float h = a / (1.f + expf(-a));
            uint32_t hb = cvt_tf32(h);
            if (jj < 32) HK[e * 33 + j] = hb;
            else         HV[e * 33 + j] = hb;
        }
        __syncthreads();

        // ---- P2: mma.sync tf32 weight-gen, store transposed via perm ----
        if (wid < 15) {
            const bool isv = (wid >= 5);
            const uint32_t* Hs = isv ? HV : HK;
            const uint32_t* Bs = (const uint32_t*)(sm + (isv ? SB_BV : SB_BK));
            const int pitch = isv ? 648 : 328;
            const int nbase = isv ? (wid - 5) * 64 : wid * 64;
            const int wcol0 = isv ? 320 + nbase : nbase;
            const int tq = lane >> 2, tr = lane & 3;

            uint32_t a[4][4];
#pragma unroll
            for (int kc = 0; kc < 4; kc++) {
                int k0 = kc * 8;
                a[kc][0] = Hs[tq * 33 + k0 + tr];
                a[kc][1] = Hs[(tq + 8) * 33 + k0 + tr];
                a[kc][2] = Hs[tq * 33 + k0 + tr + 4];
                a[kc][3] = Hs[(tq + 8) * 33 + k0 + tr + 4];
            }
#pragma unroll
            for (int nc = 0; nc < 8; nc++) {
                int n0 = nbase + nc * 8;
                float c0 = 0.f, c1 = 0.f, c2 = 0.f, c3 = 0.f;
#pragma unroll
                for (int kc = 0; kc < 4; kc++) {
                    uint32_t b0 = Bs[(kc * 8 + tr) * pitch + n0 + tq];
                    uint32_t b1 = Bs[(kc * 8 + tr + 4) * pitch + n0 + tq];
                    asm volatile(
                        "mma.sync.aligned.m16n8k8.row.col.f32.tf32.tf32.f32 "
                        "{%0,%1,%2,%3}, {%4,%5,%6,%7}, {%8,%9}, {%0,%1,%2,%3};"
                        : "+f"(c0), "+f"(c1), "+f"(c2), "+f"(c3)
                        : "r"(a[kc][0]), "r"(a[kc][1]), "r"(a[kc][2]), "r"(a[kc][3]),
                          "r"(b0), "r"(b1));
                }
                float* W = sm + SB_W;
                int colA = wcol0 + nc * 8 + 2 * tr;
                int pA = perm[colA], pB = perm[colA + 1];
                W[tq * WP + pA]       = c0 * ISQ32;
                W[tq * WP + pB]       = c1 * ISQ32;
                W[(tq + 8) * WP + pA] = c2 * ISQ32;
                W[(tq + 8) * WP + pB] = c3 * ISQ32;
            }
        }
        __syncthreads();

        // ---- P3: warp per edge (16 warps, 16 edges), vectorized LDS ----
        {
            const int le = wid;
            const int eg = ebase + le;
            const bool active = (eg < E);
            const int snd = ixs[le];
            const int rcv = ixr[le];
            const float* nf = node_ft + (size_t)snd * 40;
            const float shs  = sm[SB_SH + le * 4 + 0];
            const float shv0 = sm[SB_SH + le * 4 + 1];
            const float shv1 = sm[SB_SH + le * 4 + 2];
            const float shv2 = sm[SB_SH + le * 4 + 3];
            float* P = sm + SB_P + le * 96;

            if (lane < 16) {
                float xs = nf[lane];
                P[lane]      = xs;
                P[44 + lane] = xs * shs;
            } else if (lane < 24) {
                int i = lane - 16;
                float v0 = nf[16 + i * 3 + 0];
                float v1 = nf[16 + i * 3 + 1];
                float v2 = nf[16 + i * 3 + 2];
                P[16 + 0 * 8 + i] = v0; P[16 + 1 * 8 + i] = v1; P[16 + 2 * 8 + i] = v2;
                P[60 + i] = (v0 * shv0 + v1 * shv1 + v2 * shv2) * ISQ3;
                P[68 + 0 * 8 + i] = (v1 * shv2 - v2 * shv1) * ISQ2;
                P[68 + 1 * 8 + i] = (v2 * shv0 - v0 * shv2) * ISQ2;
                P[68 + 2 * 8 + i] = (v0 * shv1 - v1 * shv0) * ISQ2;
            } else if (lane == 24) {
                P[40] = shs; P[41] = shv0; P[42] = shv1; P[43] = shv2;
            }
            __syncwarp();

            const float* Wt = sm + SB_W + le * WP;
            float* K = sm + SB_K + le * 20;
            const float4* XS4  = (const float4*)(P);
            const float4* PSS4 = (const float4*)(P + 44);
            const float4* PVV4 = (const float4*)(P + 60);

            if (lane < 8) {
                int o = lane;
                const float4* w1 = (const float4*)(Wt + o * 16);
                const float4* w2 = (const float4*)(Wt + 128 + o * 8);
                float acc = 0.f;
#pragma unroll
                for (int i = 0; i < 4; i++) acc += dot4(PSS4[i], w1[i]);
#pragma unroll
                for (int i = 0; i < 2; i++) acc += dot4(PVV4[i], w2[i]);
                K[o] = acc * ISQ24;
            } else if (lane < 20) {
                int tt = lane - 8; int o = tt / 3; int c = tt % 3;
                const float4* w3 = (const float4*)(Wt + 192 + o * 16);
                const float4* w4 = (const float4*)(Wt + 256 + o * 8);
                const float4* w5 = (const float4*)(Wt + 288 + o * 8);
                const float4* XV4  = (const float4*)(P + 16 + c * 8);
                const float4* PXX4 = (const float4*)(P + 68 + c * 8);
                float a = 0.f, b = 0.f, cx = 0.f;
#pragma unroll
                for (int i = 0; i < 4; i++) a  += dot4(XS4[i], w3[i]);
#pragma unroll
                for (int i = 0; i < 2; i++) b  += dot4(XV4[i], w4[i]);
#pragma unroll
                for (int i = 0; i < 2; i++) cx += dot4(PXX4[i], w5[i]);
                K[8 + tt] = (P[41 + c] * a + P[40] * b + cx) * ISQ32;
            }

            if (lane < 16) {
                int o = lane;
                const float4* w1 = (const float4*)(Wt + 320 + o * 16);
                const float4* w2 = (const float4*)(Wt + 576 + o * 8);
                float acc = 0.f;
#pragma unroll
                for (int i = 0; i < 4; i++) acc += dot4(PSS4[i], w1[i]);
#pragma unroll
                for (int i = 0; i < 2; i++) acc += dot4(PVV4[i], w2[i]);
                if (active) g_v[(size_t)eg * 40 + o] = acc * ISQ24;
            }
            {
                int tt = (lane >= 16) ? (lane - 16) : (lane + 16);
                if (tt < 24) {
                    int o = tt / 3, c = tt % 3;
                    const float4* w3 = (const float4*)(Wt + 704 + o * 16);
                    const float4* w4 = (const float4*)(Wt + 832 + o * 8);
                    const float4* w5 = (const float4*)(Wt + 896 + o * 8);
                    const float4* XV4  = (const float4*)(P + 16 + c * 8);
                    const float4* PXX4 = (const float4*)(P + 68 + c * 8);
                    float a = 0.f, b = 0.f, cx = 0.f;
#pragma unroll
                    for (int i = 0; i < 4; i++) a  += dot4(XS4[i], w3[i]);
#pragma unroll
                    for (int i = 0; i < 2; i++) b  += dot4(XV4[i], w4[i]);
#pragma unroll
                    for (int i = 0; i < 2; i++) cx += dot4(PXX4[i], w5[i]);
                    float vv = (P[41 + c] * a + P[40] * b + cx) * ISQ32;
                    if (active) g_v[(size_t)eg * 40 + 16 + tt] = vv;
                }
            }
            __syncwarp();

            const float* qr = g_q + (size_t)rcv * 20;
            float d = 0.f;
            {
                int term = lane;
                int i = term >> 3, j = term & 7;
                d += qr[i] * K[j] * sm[SB_WDS + i * 8 + j];
                term += 32; i = term >> 3; j = term & 7;
                d += qr[i] * K[j] * sm[SB_WDS + i * 8 + j];
            }
            if (lane < 16) {
                int i = lane >> 2, j = lane & 3;
                float s = qr[8 + i * 3 + 0] * K[8 + j * 3 + 0]
                        + qr[8 + i * 3 + 1] * K[8 + j * 3 + 1]
                        + qr[8 + i * 3 + 2] * K[8 + j * 3 + 2];
                d += s * sm[SB_WDV + i * 4 + j] * ISQ3;
            }
#pragma unroll
            for (int off = 16; off; off >>= 1) d += __shfl_xor_sync(0xffffffffu, d, off);
            if (lane == 0 && active) {
                d *= 0.11180339887498948f;
                float ex = expf(d);
                g_ex[eg] = ex;
                atomicAdd(&g_z[rcv], ex);
            }
        }
        __syncthreads();
    }
}

// ---------------------------------------------------------------------------
__global__ void k_alpha(const int* __restrict__ eidx, int E)
{
    int e = blockIdx.x * blockDim.x + threadIdx.x;
    if (e >= E) return;
    g_ex[e] = sqrtf(__fdividef(g_ex[e], g_z[eidx[E + e]]));
}

// ---------------------------------------------------------------------------
__global__ void k_scatter(const int* __restrict__ eidx, float* __restrict__ out, int E)
{
    int idx = blockIdx.x * blockDim.x + threadIdx.x;
    int e = idx / 10, q = idx % 10;
    if (e >= E) return;
    int rcv = eidx[E + e];
    float a = g_ex[e];
    float4 v = *reinterpret_cast<const float4*>(&g_v[(size_t)e * 40 + q * 4]);
    float* dst = &out[(size_t)rcv * 40 + q * 4];
    asm volatile("red.global.add.v4.f32 [%0], {%1, %2, %3, %4};"
                 :: "l"(dst), "f"(a * v.x), "f"(a * v.y), "f"(a * v.z), "f"(a * v.w)
                 : "memory");
}

// ---------------------------------------------------------------------------
extern "C" void kernel_launch(void* const* d_in, const int* in_sizes, int n_in,
                              void* d_out, int out_size)
{
    const float* node_ft = (const float*)d_in[0];
    const int*   eidx    = (const int*)d_in[1];
    const float* edge_sh = (const float*)d_in[2];
    const float* edge_sc = (const float*)d_in[3];
    const float* wqs     = (const float*)d_in[4];
    const float* wqv     = (const float*)d_in[5];
    const float* fck_w1  = (const float*)d_in[6];
    const float* fck_w2  = (const float*)d_in[7];
    const float* fcv_w1  = (const float*)d_in[8];
    const float* fcv_w2  = (const float*)d_in[9];
    const float* wdot_s  = (const float*)d_in[10];
    const float* wdot_v  = (const float*)d_in[11];
    float* out = (float*)d_out;

    int N = in_sizes[0] / 40;
    int E = in_sizes[1] / 2;

    cudaFuncSetAttribute(k_edges, cudaFuncAttributeMaxDynamicSharedMemorySize, SMEM_BYTES);

    k_prep<<<(32 * 328 + 32 * 648 + 255) / 256, 256>>>(fck_w2, fcv_w2);
    k_nodes<<<(N + 63) / 64, 64>>>(node_ft, wqs, wqv, out, N);
    k_edges<<<148, 512, SMEM_BYTES>>>(node_ft, eidx, edge_sh, edge_sc,
                                      fck_w1, fcv_w1, wdot_s, wdot_v, E);
    k_alpha<<<(E + 255) / 256, 256>>>(eidx, E);
    k_scatter<<<((long long)E * 10 + 255) / 256, 256>>>(eidx, out, E);
}

// round 11
// speedup vs baseline: 1.4204x; 1.4204x over previous
#include <cuda_runtime.h>
#include <math.h>
#include <stdint.h>

#define N_MAX 10000
#define E_MAX 100000

// Scratch (no cudaMalloc allowed)
__device__ float g_q[N_MAX * 20];
__device__ float g_z[N_MAX];
__device__ float g_ex[E_MAX];
__device__ float g_v[(size_t)E_MAX * 40];
__device__ uint32_t g_bk[32 * 328];   // W2k tf32 bits, [k][n] pitch 328
__device__ uint32_t g_bv[32 * 648];   // W2v tf32 bits, [k][n] pitch 648

__device__ __forceinline__ uint32_t cvt_tf32(float x) {
    uint32_t r; asm("cvt.rna.tf32.f32 %0, %1;" : "=r"(r) : "f"(x)); return r;
}

// ---------------------------------------------------------------------------
// Prep: convert W2 to tf32 bit layout with conflict-free pitches
// ---------------------------------------------------------------------------
__global__ void k_prep(const float* __restrict__ fck_w2, const float* __restrict__ fcv_w2)
{
    int idx = blockIdx.x * blockDim.x + threadIdx.x;
    if (idx < 32 * 328) {
        int k = idx / 328, n = idx % 328;
        g_bk[idx] = (n < 320) ? cvt_tf32(fck_w2[k * 320 + n]) : 0u;
    }
    idx -= 32 * 328;
    if (idx >= 0 && idx < 32 * 648) {
        int k = idx / 648, n = idx % 648;
        g_bv[idx] = (n < 640) ? cvt_tf32(fcv_w2[k * 640 + n]) : 0u;
    }
}

// ---------------------------------------------------------------------------
// Kernel 0: per-node q projection, zero z and out
// ---------------------------------------------------------------------------
__global__ void __launch_bounds__(64) k_nodes(const float* __restrict__ node_ft,
                        const float* __restrict__ wqs, const float* __restrict__ wqv,
                        float* __restrict__ out, int N)
{
    int n = blockIdx.x * blockDim.x + threadIdx.x;
    if (n >= N) return;
    const float* x = node_ft + (size_t)n * 40;
    float xs[16], xv[24];
#pragma unroll
    for (int i = 0; i < 16; i++) xs[i] = x[i];
#pragma unroll
    for (int i = 0; i < 24; i++) xv[i] = x[16 + i];
    const float s0 = 0.25f, s1 = 0.35355339059327373f;
    float q[20];
#pragma unroll
    for (int o = 0; o < 8; o++) {
        float a = 0.f;
#pragma unroll
        for (int i = 0; i < 16; i++) a += xs[i] * wqs[i * 8 + o];
        q[o] = a * s0;
    }
#pragma unroll
    for (int o = 0; o < 4; o++)
#pragma unroll
        for (int c = 0; c < 3; c++) {
            float a = 0.f;
#pragma unroll
            for (int i = 0; i < 8; i++) a += xv[i * 3 + c] * wqv[i * 4 + o];
            q[8 + o * 3 + c] = a * s1;
        }
#pragma unroll
    for (int i = 0; i < 20; i++) g_q[(size_t)n * 20 + i] = q[i];
    g_z[n] = 0.f;
    float4 z4 = make_float4(0.f, 0.f, 0.f, 0.f);
#pragma unroll
    for (int i = 0; i < 10; i++)
        *reinterpret_cast<float4*>(&out[(size_t)n * 40 + i * 4]) = z4;
}

// ---------------------------------------------------------------------------
// Main kernel: persistent, 16 edges/tile, mma.sync tf32 weight-gen.
// W tile: [e][col 0..959], pitch 970 (conflict-engineered), R9 column layout:
//   k: w1[16x8]@0 w2[8x8]@128 w3[16x4]@192 w4[8x4]@256 w5[8x4]@288
//   v(+320): w1[16x16]@0 w2[8x16]@256 w3[16x8]@384 w4[8x8]@512 w5[8x8]@576
// P per edge, pitch 97: XS@0(16) XVt@16([c][8]) PSS@44(16) PVV@60(8) PXXt@68([c][8])
// Epilogue: thread (e = tid&15, part = tid>>4); warp-uniform part groups.
// ---------------------------------------------------------------------------
#define SB_BK   0          // 32 x 328 (tf32 bits)
#define SB_BV   10496      // 32 x 648
#define SB_W    31232      // 16 x 970
#define SB_HK   46752      // 16 x 33 (tf32 bits)
#define SB_HV   47280      // 16 x 33
#define SB_W1K  47808      // 512
#define SB_W1V  48320      // 512
#define SB_WDS  48832      // 64
#define SB_WDV  48896      // 16
#define SB_ES   48912      // 16 x 16
#define SB_SH   49168      // 16 x 4
#define SB_IX   49232      // 32 ints
#define SB_P    49264      // 16 x 97
#define SB_K    50816      // 16 x 21
#define SMEM_FLOATS 51152
#define SMEM_BYTES (SMEM_FLOATS * 4)
#define WP 970

__global__ void __launch_bounds__(512, 1) k_edges(
    const float* __restrict__ node_ft,
    const int* __restrict__ eidx,
    const float* __restrict__ edge_sh,
    const float* __restrict__ edge_sc,
    const float* __restrict__ fck_w1,
    const float* __restrict__ fcv_w1,
    const float* __restrict__ wdot_s,
    const float* __restrict__ wdot_v,
    int E)
{
    extern __shared__ float sm[];
    const int tid  = threadIdx.x;
    const int wid  = tid >> 5;
    const int lane = tid & 31;

    // ---- startup: stage B (tf32 W2), W1, wdot ----
    {
        uint32_t* bk = (uint32_t*)(sm + SB_BK);
        uint32_t* bv = (uint32_t*)(sm + SB_BV);
        for (int i = tid; i < 32 * 328; i += 512) bk[i] = g_bk[i];
        for (int i = tid; i < 32 * 648; i += 512) bv[i] = g_bv[i];
        sm[SB_W1K + tid] = fck_w1[tid];
        sm[SB_W1V + tid] = fcv_w1[tid];
        if (tid < 64) sm[SB_WDS + tid] = wdot_s[tid];
        if (tid < 16) sm[SB_WDV + tid] = wdot_v[tid];
    }
    __syncthreads();

    const float ISQ32 = 0.17677669529663687f;
    const float ISQ24 = 0.2041241452319315f;
    const float ISQ3  = 0.5773502691896258f;
    const float ISQ2  = 0.7071067811865476f;

    int* ixs = (int*)(sm + SB_IX);
    int* ixr = (int*)(sm + SB_IX + 16);
    const int ntiles = (E + 15) >> 4;

    for (int t = blockIdx.x; t < ntiles; t += 148) {
        const int ebase = t << 4;

        // ---- stage edge data ----
        if (tid < 256) {
            int e = tid >> 4, i = tid & 15;
            int eg = min(ebase + e, E - 1);
            sm[SB_ES + tid] = edge_sc[(size_t)eg * 16 + i];
        } else if (tid < 288) {
            int f = tid - 256;
            int e = f & 15;
            int eg = min(ebase + e, E - 1);
            if (f < 16) ixs[e] = eidx[eg];
            else        ixr[e] = eidx[E + eg];
        } else if (tid < 352) {
            int f = tid - 288;
            int eg = min(ebase + (f >> 2), E - 1);
            sm[SB_SH + f] = edge_sh[(size_t)eg * 4 + (f & 3)];
        }
        __syncthreads();

        // ---- P1: hidden activations -> tf32 bits in HK/HV ----
        uint32_t* HK = (uint32_t*)(sm + SB_HK);
        uint32_t* HV = (uint32_t*)(sm + SB_HV);
#pragma unroll
        for (int s = 0; s < 2; s++) {
            int task = tid + s * 512;
            int e = task >> 6, jj = task & 63, j = jj & 31;
            const float* W1 = sm + ((jj < 32) ? SB_W1K : SB_W1V);
            const float* es = sm + SB_ES + e * 16;
            float a = 0.f;
#pragma unroll
            for (int i = 0; i < 16; i++) a += es[i] * W1[i * 32 + j];
            a *= 0.25f;
            float h = a / (1.f + expf(-a));
            uint32_t hb = cvt_tf32(h);
            if (jj < 32) HK[e * 33 + j] = hb;
            else         HV[e * 33 + j] = hb;
        }
        __syncthreads();

        // ---- P-feature build (all threads) + P2 mma (warps 0..14) ----
        {
            const int e = tid & 15, r = tid >> 4;
            const int snd = ixs[e];
            const float* nf = node_ft + (size_t)snd * 40;
            float* Pe = sm + SB_P + e * 97;
            if (r < 16) {
                float xs = nf[r];
                float shs = sm[SB_SH + e * 4];
                Pe[r]      = xs;
                Pe[44 + r] = xs * shs;
            } else if (r < 24) {
                int i = r - 16;
                float shv0 = sm[SB_SH + e * 4 + 1];
                float shv1 = sm[SB_SH + e * 4 + 2];
                float shv2 = sm[SB_SH + e * 4 + 3];
                float v0 = nf[16 + i * 3 + 0];
                float v1 = nf[16 + i * 3 + 1];
                float v2 = nf[16 + i * 3 + 2];
                Pe[16 + 0 * 8 + i] = v0;
                Pe[16 + 1 * 8 + i] = v1;
                Pe[16 + 2 * 8 + i] = v2;
                Pe[60 + i] = (v0 * shv0 + v1 * shv1 + v2 * shv2) * ISQ3;
                Pe[68 + 0 * 8 + i] = (v1 * shv2 - v2 * shv1) * ISQ2;
                Pe[68 + 1 * 8 + i] = (v2 * shv0 - v0 * shv2) * ISQ2;
                Pe[68 + 2 * 8 + i] = (v0 * shv1 - v1 * shv0) * ISQ2;
            }
        }
        if (wid < 15) {
            const bool isv = (wid >= 5);
            const uint32_t* Hs = (const uint32_t*)(sm + (isv ? SB_HV : SB_HK));
            const uint32_t* Bs = (const uint32_t*)(sm + (isv ? SB_BV : SB_BK));
            const int pitch = isv ? 648 : 328;
            const int nbase = isv ? (wid - 5) * 64 : wid * 64;
            const int wcol0 = isv ? 320 + nbase : nbase;
            const int tq = lane >> 2, tr = lane & 3;

            uint32_t a[4][4];
#pragma unroll
            for (int kc = 0; kc < 4; kc++) {
                int k0 = kc * 8;
                a[kc][0] = Hs[tq * 33 + k0 + tr];
                a[kc][1] = Hs[(tq + 8) * 33 + k0 + tr];
                a[kc][2] = Hs[tq * 33 + k0 + tr + 4];
                a[kc][3] = Hs[(tq + 8) * 33 + k0 + tr + 4];
            }
#pragma unroll
            for (int nc = 0; nc < 8; nc++) {
                int n0 = nbase + nc * 8;
                float c0 = 0.f, c1 = 0.f, c2 = 0.f, c3 = 0.f;
#pragma unroll
                for (int kc = 0; kc < 4; kc++) {
                    uint32_t b0 = Bs[(kc * 8 + tr) * pitch + n0 + tq];
                    uint32_t b1 = Bs[(kc * 8 + tr + 4) * pitch + n0 + tq];
                    asm volatile(
                        "mma.sync.aligned.m16n8k8.row.col.f32.tf32.tf32.f32 "
                        "{%0,%1,%2,%3}, {%4,%5,%6,%7}, {%8,%9}, {%0,%1,%2,%3};"
                        : "+f"(c0), "+f"(c1), "+f"(c2), "+f"(c3)
                        : "r"(a[kc][0]), "r"(a[kc][1]), "r"(a[kc][2]), "r"(a[kc][3]),
                          "r"(b0), "r"(b1));
                }
                float* W = sm + SB_W;
                int col = wcol0 + nc * 8 + 2 * tr;
                *reinterpret_cast<float2*>(&W[tq * WP + col]) =
                    make_float2(c0 * ISQ32, c1 * ISQ32);
                *reinterpret_cast<float2*>(&W[(tq + 8) * WP + col]) =
                    make_float2(c2 * ISQ32, c3 * ISQ32);
            }
        }
        __syncthreads();

        // ---- P3: uniform part-mapped epilogue ----
        {
            const int e = tid & 15, part = tid >> 4;
            const int eg = ebase + e;
            const bool active = (eg < E);
            const float* Pe = sm + SB_P + e * 97;
            const float* Wt = sm + SB_W + e * WP;

            if (part < 8) {
                // k_s[part] and v_s[part]
                int o = part;
                float acc = 0.f;
#pragma unroll
                for (int i = 0; i < 16; i++) acc += Pe[44 + i] * Wt[i * 8 + o];
#pragma unroll
                for (int i = 0; i < 8;  i++) acc += Pe[60 + i] * Wt[128 + i * 8 + o];
                sm[SB_K + e * 21 + o] = acc * ISQ24;

                float acc2 = 0.f;
#pragma unroll
                for (int i = 0; i < 16; i++) acc2 += Pe[44 + i] * Wt[320 + i * 16 + o];
#pragma unroll
                for (int i = 0; i < 8;  i++) acc2 += Pe[60 + i] * Wt[576 + i * 16 + o];
                if (active) g_v[(size_t)eg * 40 + o] = acc2 * ISQ24;
            } else if (part < 20) {
                // k_v[t] and v_v[t], t = part-8
                int tt = part - 8, o = tt / 3, c = tt - 3 * o;
                float shs  = sm[SB_SH + e * 4];
                float shvc = sm[SB_SH + e * 4 + 1 + c];
                float a = 0.f, b = 0.f, cx = 0.f;
#pragma unroll
                for (int i = 0; i < 16; i++) a  += Pe[i]            * Wt[192 + i * 4 + o];
#pragma unroll
                for (int i = 0; i < 8;  i++) b  += Pe[16 + c * 8 + i] * Wt[256 + i * 4 + o];
#pragma unroll
                for (int i = 0; i < 8;  i++) cx += Pe[68 + c * 8 + i] * Wt[288 + i * 4 + o];
                sm[SB_K + e * 21 + 8 + tt] = (shvc * a + shs * b + cx) * ISQ32;

                float a2 = 0.f, b2 = 0.f, cx2 = 0.f;
#pragma unroll
                for (int i = 0; i < 16; i++) a2  += Pe[i]            * Wt[704 + i * 8 + o];
#pragma unroll
                for (int i = 0; i < 8;  i++) b2  += Pe[16 + c * 8 + i] * Wt[832 + i * 8 + o];
#pragma unroll
                for (int i = 0; i < 8;  i++) cx2 += Pe[68 + c * 8 + i] * Wt[896 + i * 8 + o];
                if (active) g_v[(size_t)eg * 40 + 16 + tt] = (shvc * a2 + shs * b2 + cx2) * ISQ32;
            } else if (part < 28) {
                // v_s[8+(part-20)] and v_v[12+(part-20)]
                int o = 8 + (part - 20);
                float acc2 = 0.f;
#pragma unroll
                for (int i = 0; i < 16; i++) acc2 += Pe[44 + i] * Wt[320 + i * 16 + o];
#pragma unroll
                for (int i = 0; i < 8;  i++) acc2 += Pe[60 + i] * Wt[576 + i * 16 + o];
                if (active) g_v[(size_t)eg * 40 + o] = acc2 * ISQ24;

                int tt = 12 + (part - 20), o2 = tt / 3, c = tt - 3 * o2;
                float shs  = sm[SB_SH + e * 4];
                float shvc = sm[SB_SH + e * 4 + 1 + c];
                float a2 = 0.f, b2 = 0.f, cx2 = 0.f;
#pragma unroll
                for (int i = 0; i < 16; i++) a2  += Pe[i]            * Wt[704 + i * 8 + o2];
#pragma unroll
                for (int i = 0; i < 8;  i++) b2  += Pe[16 + c * 8 + i] * Wt[832 + i * 8 + o2];
#pragma unroll
                for (int i = 0; i < 8;  i++) cx2 += Pe[68 + c * 8 + i] * Wt[896 + i * 8 + o2];
                if (active) g_v[(size_t)eg * 40 + 16 + tt] = (shvc * a2 + shs * b2 + cx2) * ISQ32;
            } else {
                // v_v[20+(part-28)]
                int tt = 20 + (part - 28), o2 = tt / 3, c = tt - 3 * o2;
                float shs  = sm[SB_SH + e * 4];
                float shvc = sm[SB_SH + e * 4 + 1 + c];
                float a2 = 0.f, b2 = 0.f, cx2 = 0.f;
#pragma unroll
                for (int i = 0; i < 16; i++) a2  += Pe[i]            * Wt[704 + i * 8 + o2];
#pragma unroll
                for (int i = 0; i < 8;  i++) b2  += Pe[16 + c * 8 + i] * Wt[832 + i * 8 + o2];
#pragma unroll
                for (int i = 0; i < 8;  i++) cx2 += Pe[68 + c * 8 + i] * Wt[896 + i * 8 + o2];
                if (active) g_v[(size_t)eg * 40 + 16 + tt] = (shvc * a2 + shs * b2 + cx2) * ISQ32;
            }
        }
        __syncthreads();

        // ---- dot(q[recv], k): warp per edge (R9 structure) ----
        {
            const int le = wid;
            const int eg = ebase + le;
            const bool active = (eg < E);
            const int rcv = ixr[le];
            const float* K = sm + SB_K + le * 21;
            const float* qr = g_q + (size_t)rcv * 20;
            float d = 0.f;
            {
                int term = lane;
                int i = term >> 3, j = term & 7;
                d += qr[i] * K[j] * sm[SB_WDS + i * 8 + j];
                term += 32; i = term >> 3; j = term & 7;
                d += qr[i] * K[j] * sm[SB_WDS + i * 8 + j];
            }
            if (lane < 16) {
                int i = lane >> 2, j = lane & 3;
                float s = qr[8 + i * 3 + 0] * K[8 + j * 3 + 0]
                        + qr[8 + i * 3 + 1] * K[8 + j * 3 + 1]
                        + qr[8 + i * 3 + 2] * K[8 + j * 3 + 2];
                d += s * sm[SB_WDV + i * 4 + j] * ISQ3;
            }
#pragma unroll
            for (int off = 16; off; off >>= 1) d += __shfl_xor_sync(0xffffffffu, d, off);
            if (lane == 0 && active) {
                d *= 0.11180339887498948f;
                float ex = expf(d);
                g_ex[eg] = ex;
                atomicAdd(&g_z[rcv], ex);
            }
        }
        __syncthreads();
    }
}

// ---------------------------------------------------------------------------
__global__ void k_alpha(const int* __restrict__ eidx, int E)
{
    int e = blockIdx.x * blockDim.x + threadIdx.x;
    if (e >= E) return;
    g_ex[e] = sqrtf(__fdividef(g_ex[e], g_z[eidx[E + e]]));
}

// ---------------------------------------------------------------------------
__global__ void k_scatter(const int* __restrict__ eidx, float* __restrict__ out, int E)
{
    int idx = blockIdx.x * blockDim.x + threadIdx.x;
    int e = idx / 10, q = idx % 10;
    if (e >= E) return;
    int rcv = eidx[E + e];
    float a = g_ex[e];
    float4 v = *reinterpret_cast<const float4*>(&g_v[(size_t)e * 40 + q * 4]);
    float* dst = &out[(size_t)rcv * 40 + q * 4];
    asm volatile("red.global.add.v4.f32 [%0], {%1, %2, %3, %4};"
                 :: "l"(dst), "f"(a * v.x), "f"(a * v.y), "f"(a * v.z), "f"(a * v.w)
                 : "memory");
}

// ---------------------------------------------------------------------------
extern "C" void kernel_launch(void* const* d_in, const int* in_sizes, int n_in,
                              void* d_out, int out_size)
{
    const float* node_ft = (const float*)d_in[0];
    const int*   eidx    = (const int*)d_in[1];
    const float* edge_sh = (const float*)d_in[2];
    const float* edge_sc = (const float*)d_in[3];
    const float* wqs     = (const float*)d_in[4];
    const float* wqv     = (const float*)d_in[5];
    const float* fck_w1  = (const float*)d_in[6];
    const float* fck_w2  = (const float*)d_in[7];
    const float* fcv_w1  = (const float*)d_in[8];
    const float* fcv_w2  = (const float*)d_in[9];
    const float* wdot_s  = (const float*)d_in[10];
    const float* wdot_v  = (const float*)d_in[11];
    float* out = (float*)d_out;

    int N = in_sizes[0] / 40;
    int E = in_sizes[1] / 2;

    cudaFuncSetAttribute(k_edges, cudaFuncAttributeMaxDynamicSharedMemorySize, SMEM_BYTES);

    k_prep<<<(32 * 328 + 32 * 648 + 255) / 256, 256>>>(fck_w2, fcv_w2);
    k_nodes<<<(N + 63) / 64, 64>>>(node_ft, wqs, wqv, out, N);
    k_edges<<<148, 512, SMEM_BYTES>>>(node_ft, eidx, edge_sh, edge_sc,
                                      fck_w1, fcv_w1, wdot_s, wdot_v, E);
    k_alpha<<<(E + 255) / 256, 256>>>(eidx, E);
    k_scatter<<<((long long)E * 10 + 255) / 256, 256>>>(eidx, out, E);
}

// round 12
// speedup vs baseline: 1.6278x; 1.1460x over previous
#include <cuda_runtime.h>
#include <math.h>
#include <stdint.h>

#define N_MAX 10000
#define E_MAX 100000

// Scratch (no cudaMalloc allowed)
__device__ float g_q[N_MAX * 20];
__device__ float g_z[N_MAX];
__device__ float g_ex[E_MAX];
__device__ float g_v[(size_t)E_MAX * 40];

__device__ __forceinline__ uint32_t cvt_tf32(float x) {
    uint32_t r; asm("cvt.rna.tf32.f32 %0, %1;" : "=r"(r) : "f"(x)); return r;
}

// ---------------------------------------------------------------------------
// Kernel 0: per-node q projection, zero z and out
// ---------------------------------------------------------------------------
__global__ void __launch_bounds__(64) k_nodes(const float* __restrict__ node_ft,
                        const float* __restrict__ wqs, const float* __restrict__ wqv,
                        float* __restrict__ out, int N)
{
    int n = blockIdx.x * blockDim.x + threadIdx.x;
    if (n >= N) return;
    const float* x = node_ft + (size_t)n * 40;
    float xs[16], xv[24];
#pragma unroll
    for (int i = 0; i < 16; i++) xs[i] = x[i];
#pragma unroll
    for (int i = 0; i < 24; i++) xv[i] = x[16 + i];
    const float s0 = 0.25f, s1 = 0.35355339059327373f;
    float q[20];
#pragma unroll
    for (int o = 0; o < 8; o++) {
        float a = 0.f;
#pragma unroll
        for (int i = 0; i < 16; i++) a += xs[i] * wqs[i * 8 + o];
        q[o] = a * s0;
    }
#pragma unroll
    for (int o = 0; o < 4; o++)
#pragma unroll
        for (int c = 0; c < 3; c++) {
            float a = 0.f;
#pragma unroll
            for (int i = 0; i < 8; i++) a += xv[i * 3 + c] * wqv[i * 4 + o];
            q[8 + o * 3 + c] = a * s1;
        }
#pragma unroll
    for (int i = 0; i < 20; i++) g_q[(size_t)n * 20 + i] = q[i];
    g_z[n] = 0.f;
    float4 z4 = make_float4(0.f, 0.f, 0.f, 0.f);
#pragma unroll
    for (int i = 0; i < 10; i++)
        *reinterpret_cast<float4*>(&out[(size_t)n * 40 + i * 4]) = z4;
}

// ---------------------------------------------------------------------------
// Main kernel: persistent, 16 edges/tile, mma.sync tf32 weight-gen.
//   B fragments register-resident (loaded once); gathers prefetched.
// W tile: [e][col 0..959], pitch 970, R9 column layout:
//   k: w1[16x8]@0 w2[8x8]@128 w3[16x4]@192 w4[8x4]@256 w5[8x4]@288
//   v(+320): w1[16x16]@0 w2[8x16]@256 w3[16x8]@384 w4[8x8]@512 w5[8x8]@576
// ---------------------------------------------------------------------------
#define SB_W    0          // 16 x 970
#define SB_HK   15520      // 16 x 33 (tf32 bits)
#define SB_HV   16048      // 16 x 33
#define SB_W1K  16576      // 512
#define SB_W1V  17088      // 512
#define SB_WDS  17600      // 64
#define SB_WDV  17664      // 16
#define SB_ES   17680      // 16 x 16
#define SB_SH   17936      // 16 x 4
#define SB_IX   18000      // 32 ints
#define SB_P    18032      // 16 x 97
#define SB_K    19584      // 16 x 21
#define SB_QR   19920      // 16 x 21
#define SMEM_FLOATS 20256
#define SMEM_BYTES (SMEM_FLOATS * 4)
#define WP 970

__global__ void __launch_bounds__(512, 1) k_edges(
    const float* __restrict__ node_ft,
    const int* __restrict__ eidx,
    const float* __restrict__ edge_sh,
    const float* __restrict__ edge_sc,
    const float* __restrict__ fck_w1,
    const float* __restrict__ fck_w2,
    const float* __restrict__ fcv_w1,
    const float* __restrict__ fcv_w2,
    const float* __restrict__ wdot_s,
    const float* __restrict__ wdot_v,
    int E)
{
    extern __shared__ float sm[];
    const int tid  = threadIdx.x;
    const int wid  = tid >> 5;
    const int lane = tid & 31;

    // ---- startup: B fragments -> registers (tile-invariant), W1/wdot -> smem
    const bool isv = (wid >= 5);
    const int tq = lane >> 2, tr = lane & 3;
    uint32_t bfrag[8][4][2];
    if (wid < 15) {
        const float* W2 = isv ? fcv_w2 : fck_w2;
        const int pitch = isv ? 640 : 320;
        const int nbase = isv ? (wid - 5) * 64 : wid * 64;
#pragma unroll
        for (int nc = 0; nc < 8; nc++) {
            int n0 = nbase + nc * 8;
#pragma unroll
            for (int kc = 0; kc < 4; kc++) {
                bfrag[nc][kc][0] = cvt_tf32(__ldg(&W2[(kc * 8 + tr) * pitch + n0 + tq]));
                bfrag[nc][kc][1] = cvt_tf32(__ldg(&W2[(kc * 8 + tr + 4) * pitch + n0 + tq]));
            }
        }
    }
    sm[SB_W1K + tid] = fck_w1[tid];
    sm[SB_W1V + tid] = fcv_w1[tid];
    if (tid < 64) sm[SB_WDS + tid] = wdot_s[tid];
    if (tid < 16) sm[SB_WDV + tid] = wdot_v[tid];
    __syncthreads();

    const float ISQ32 = 0.17677669529663687f;
    const float ISQ24 = 0.2041241452319315f;
    const float ISQ3  = 0.5773502691896258f;
    const float ISQ2  = 0.7071067811865476f;

    int* ixs = (int*)(sm + SB_IX);
    int* ixr = (int*)(sm + SB_IX + 16);
    const int ntiles = (E + 15) >> 4;

    for (int t = blockIdx.x; t < ntiles; t += 148) {
        const int ebase = t << 4;

        // ---- stage edge data ----
        if (tid < 256) {
            int e = tid >> 4, i = tid & 15;
            int eg = min(ebase + e, E - 1);
            sm[SB_ES + tid] = edge_sc[(size_t)eg * 16 + i];
        } else if (tid < 288) {
            int f = tid - 256;
            int e = f & 15;
            int eg = min(ebase + e, E - 1);
            if (f < 16) ixs[e] = eidx[eg];
            else        ixr[e] = eidx[E + eg];
        } else if (tid < 352) {
            int f = tid - 288;
            int eg = min(ebase + (f >> 2), E - 1);
            sm[SB_SH + f] = edge_sh[(size_t)eg * 4 + (f & 3)];
        }
        __syncthreads();

        // ---- P1 phase: prefetch nf gathers, hidden act, stage q[recv] ----
        const int e_pf = tid & 15, r_pf = tid >> 4;
        float nfv0 = 0.f, nfv1 = 0.f, nfv2 = 0.f;
        {
            const float* nf = node_ft + (size_t)ixs[e_pf] * 40;
            if (r_pf < 16) nfv0 = __ldg(&nf[r_pf]);
            else if (r_pf < 24) {
                int i = r_pf - 16;
                nfv0 = __ldg(&nf[16 + i * 3]);
                nfv1 = __ldg(&nf[17 + i * 3]);
                nfv2 = __ldg(&nf[18 + i * 3]);
            }
        }
        uint32_t* HK = (uint32_t*)(sm + SB_HK);
        uint32_t* HV = (uint32_t*)(sm + SB_HV);
#pragma unroll
        for (int s = 0; s < 2; s++) {
            int task = tid + s * 512;
            int e = task >> 6, jj = task & 63, j = jj & 31;
            const float* W1 = sm + ((jj < 32) ? SB_W1K : SB_W1V);
            const float* es = sm + SB_ES + e * 16;
            float a = 0.f;
#pragma unroll
            for (int i = 0; i < 16; i++) a += es[i] * W1[i * 32 + j];
            a *= 0.25f;
            float h = a / (1.f + expf(-a));
            uint32_t hb = cvt_tf32(h);
            if (jj < 32) HK[e * 33 + j] = hb;
            else         HV[e * 33 + j] = hb;
        }
        if (tid < 320) {
            int e2 = tid / 20, i = tid % 20;
            sm[SB_QR + e2 * 21 + i] = g_q[(size_t)ixr[e2] * 20 + i];
        }
        __syncthreads();

        // ---- P-feature build (prefetched regs) + P2 mma ----
        {
            float* Pe = sm + SB_P + e_pf * 97;
            if (r_pf < 16) {
                float shs = sm[SB_SH + e_pf * 4];
                Pe[r_pf]      = nfv0;
                Pe[44 + r_pf] = nfv0 * shs;
            } else if (r_pf < 24) {
                int i = r_pf - 16;
                float shv0 = sm[SB_SH + e_pf * 4 + 1];
                float shv1 = sm[SB_SH + e_pf * 4 + 2];
                float shv2 = sm[SB_SH + e_pf * 4 + 3];
                Pe[16 + 0 * 8 + i] = nfv0;
                Pe[16 + 1 * 8 + i] = nfv1;
                Pe[16 + 2 * 8 + i] = nfv2;
                Pe[60 + i] = (nfv0 * shv0 + nfv1 * shv1 + nfv2 * shv2) * ISQ3;
                Pe[68 + 0 * 8 + i] = (nfv1 * shv2 - nfv2 * shv1) * ISQ2;
                Pe[68 + 1 * 8 + i] = (nfv2 * shv0 - nfv0 * shv2) * ISQ2;
                Pe[68 + 2 * 8 + i] = (nfv0 * shv1 - nfv1 * shv0) * ISQ2;
            }
        }
        if (wid < 15) {
            const uint32_t* Hs = (const uint32_t*)(sm + (isv ? SB_HV : SB_HK));
            const int nbase = isv ? (wid - 5) * 64 : wid * 64;
            const int wcol0 = isv ? 320 + nbase : nbase;

            uint32_t a[4][4];
#pragma unroll
            for (int kc = 0; kc < 4; kc++) {
                int k0 = kc * 8;
                a[kc][0] = Hs[tq * 33 + k0 + tr];
                a[kc][1] = Hs[(tq + 8) * 33 + k0 + tr];
                a[kc][2] = Hs[tq * 33 + k0 + tr + 4];
                a[kc][3] = Hs[(tq + 8) * 33 + k0 + tr + 4];
            }
#pragma unroll
            for (int nc = 0; nc < 8; nc++) {
                float c0 = 0.f, c1 = 0.f, c2 = 0.f, c3 = 0.f;
#pragma unroll
                for (int kc = 0; kc < 4; kc++) {
                    asm volatile(
                        "mma.sync.aligned.m16n8k8.row.col.f32.tf32.tf32.f32 "
                        "{%0,%1,%2,%3}, {%4,%5,%6,%7}, {%8,%9}, {%0,%1,%2,%3};"
                        : "+f"(c0), "+f"(c1), "+f"(c2), "+f"(c3)
                        : "r"(a[kc][0]), "r"(a[kc][1]), "r"(a[kc][2]), "r"(a[kc][3]),
                          "r"(bfrag[nc][kc][0]), "r"(bfrag[nc][kc][1]));
                }
                float* W = sm + SB_W;
                int col = wcol0 + nc * 8 + 2 * tr;
                *reinterpret_cast<float2*>(&W[tq * WP + col]) =
                    make_float2(c0 * ISQ32, c1 * ISQ32);
                *reinterpret_cast<float2*>(&W[(tq + 8) * WP + col]) =
                    make_float2(c2 * ISQ32, c3 * ISQ32);
            }
        }
        __syncthreads();

        // ---- P3: uniform part-mapped epilogue ----
        {
            const int e = tid & 15, part = tid >> 4;
            const int eg = ebase + e;
            const bool active = (eg < E);
            const float* Pe = sm + SB_P + e * 97;
            const float* Wt = sm + SB_W + e * WP;

            if (part < 8) {
                int o = part;
                float acc = 0.f;
#pragma unroll
                for (int i = 0; i < 16; i++) acc += Pe[44 + i] * Wt[i * 8 + o];
#pragma unroll
                for (int i = 0; i < 8;  i++) acc += Pe[60 + i] * Wt[128 + i * 8 + o];
                sm[SB_K + e * 21 + o] = acc * ISQ24;

                float acc2 = 0.f;
#pragma unroll
                for (int i = 0; i < 16; i++) acc2 += Pe[44 + i] * Wt[320 + i * 16 + o];
#pragma unroll
                for (int i = 0; i < 8;  i++) acc2 += Pe[60 + i] * Wt[576 + i * 16 + o];
                if (active) g_v[(size_t)eg * 40 + o] = acc2 * ISQ24;
            } else if (part < 20) {
                int tt = part - 8, o = tt / 3, c = tt - 3 * o;
                float shs  = sm[SB_SH + e * 4];
                float shvc = sm[SB_SH + e * 4 + 1 + c];
                float a = 0.f, b = 0.f, cx = 0.f;
#pragma unroll
                for (int i = 0; i < 16; i++) a  += Pe[i]              * Wt[192 + i * 4 + o];
#pragma unroll
                for (int i = 0; i < 8;  i++) b  += Pe[16 + c * 8 + i] * Wt[256 + i * 4 + o];
#pragma unroll
                for (int i = 0; i < 8;  i++) cx += Pe[68 + c * 8 + i] * Wt[288 + i * 4 + o];
                sm[SB_K + e * 21 + 8 + tt] = (shvc * a + shs * b + cx) * ISQ32;

                float a2 = 0.f, b2 = 0.f, cx2 = 0.f;
#pragma unroll
                for (int i = 0; i < 16; i++) a2  += Pe[i]              * Wt[704 + i * 8 + o];
#pragma unroll
                for (int i = 0; i < 8;  i++) b2  += Pe[16 + c * 8 + i] * Wt[832 + i * 8 + o];
#pragma unroll
                for (int i = 0; i < 8;  i++) cx2 += Pe[68 + c * 8 + i] * Wt[896 + i * 8 + o];
                if (active) g_v[(size_t)eg * 40 + 16 + tt] = (shvc * a2 + shs * b2 + cx2) * ISQ32;
            } else if (part < 28) {
                int o = 8 + (part - 20);
                float acc2 = 0.f;
#pragma unroll
                for (int i = 0; i < 16; i++) acc2 += Pe[44 + i] * Wt[320 + i * 16 + o];
#pragma unroll
                for (int i = 0; i < 8;  i++) acc2 += Pe[60 + i] * Wt[576 + i * 16 + o];
                if (active) g_v[(size_t)eg * 40 + o] = acc2 * ISQ24;

                int tt = 12 + (part - 20), o2 = tt / 3, c = tt - 3 * o2;
                float shs  = sm[SB_SH + e * 4];
                float shvc = sm[SB_SH + e * 4 + 1 + c];
                float a2 = 0.f, b2 = 0.f, cx2 = 0.f;
#pragma unroll
                for (int i = 0; i < 16; i++) a2  += Pe[i]              * Wt[704 + i * 8 + o2];
#pragma unroll
                for (int i = 0; i < 8;  i++) b2  += Pe[16 + c * 8 + i] * Wt[832 + i * 8 + o2];
#pragma unroll
                for (int i = 0; i < 8;  i++) cx2 += Pe[68 + c * 8 + i] * Wt[896 + i * 8 + o2];
                if (active) g_v[(size_t)eg * 40 + 16 + tt] = (shvc * a2 + shs * b2 + cx2) * ISQ32;
            } else {
                int tt = 20 + (part - 28), o2 = tt / 3, c = tt - 3 * o2;
                float shs  = sm[SB_SH + e * 4];
                float shvc = sm[SB_SH + e * 4 + 1 + c];
                float a2 = 0.f, b2 = 0.f, cx2 = 0.f;
#pragma unroll
                for (int i = 0; i < 16; i++) a2  += Pe[i]              * Wt[704 + i * 8 + o2];
#pragma unroll
                for (int i = 0; i < 8;  i++) b2  += Pe[16 + c * 8 + i] * Wt[832 + i * 8 + o2];
#pragma unroll
                for (int i = 0; i < 8;  i++) cx2 += Pe[68 + c * 8 + i] * Wt[896 + i * 8 + o2];
                if (active) g_v[(size_t)eg * 40 + 16 + tt] = (shvc * a2 + shs * b2 + cx2) * ISQ32;
            }
        }
        __syncthreads();

        // ---- dot(q[recv], k): warp per edge ----
        {
            const int le = wid;
            const int eg = ebase + le;
            const bool active = (eg < E);
            const float* K  = sm + SB_K  + le * 21;
            const float* qr = sm + SB_QR + le * 21;
            float d = 0.f;
            {
                int term = lane;
                int i = term >> 3, j = term & 7;
                d += qr[i] * K[j] * sm[SB_WDS + i * 8 + j];
                term += 32; i = term >> 3; j = term & 7;
                d += qr[i] * K[j] * sm[SB_WDS + i * 8 + j];
            }
            if (lane < 16) {
                int i = lane >> 2, j = lane & 3;
                float s = qr[8 + i * 3 + 0] * K[8 + j * 3 + 0]
                        + qr[8 + i * 3 + 1] * K[8 + j * 3 + 1]
                        + qr[8 + i * 3 + 2] * K[8 + j * 3 + 2];
                d += s * sm[SB_WDV + i * 4 + j] * ISQ3;
            }
#pragma unroll
            for (int off = 16; off; off >>= 1) d += __shfl_xor_sync(0xffffffffu, d, off);
            if (lane == 0 && active) {
                d *= 0.11180339887498948f;
                float ex = expf(d);
                g_ex[eg] = ex;
                atomicAdd(&g_z[ixr[le]], ex);
            }
        }
        __syncthreads();
    }
}

// ---------------------------------------------------------------------------
__global__ void k_alpha(const int* __restrict__ eidx, int E)
{
    int e = blockIdx.x * blockDim.x + threadIdx.x;
    if (e >= E) return;
    g_ex[e] = sqrtf(__fdividef(g_ex[e], g_z[eidx[E + e]]));
}

// ---------------------------------------------------------------------------
__global__ void k_scatter(const int* __restrict__ eidx, float* __restrict__ out, int E)
{
    int idx = blockIdx.x * blockDim.x + threadIdx.x;
    int e = idx / 10, q = idx % 10;
    if (e >= E) return;
    int rcv = eidx[E + e];
    float a = g_ex[e];
    float4 v = *reinterpret_cast<const float4*>(&g_v[(size_t)e * 40 + q * 4]);
    float* dst = &out[(size_t)rcv * 40 + q * 4];
    asm volatile("red.global.add.v4.f32 [%0], {%1, %2, %3, %4};"
                 :: "l"(dst), "f"(a * v.x), "f"(a * v.y), "f"(a * v.z), "f"(a * v.w)
                 : "memory");
}

// ---------------------------------------------------------------------------
extern "C" void kernel_launch(void* const* d_in, const int* in_sizes, int n_in,
                              void* d_out, int out_size)
{
    const float* node_ft = (const float*)d_in[0];
    const int*   eidx    = (const int*)d_in[1];
    const float* edge_sh = (const float*)d_in[2];
    const float* edge_sc = (const float*)d_in[3];
    const float* wqs     = (const float*)d_in[4];
    const float* wqv     = (const float*)d_in[5];
    const float* fck_w1  = (const float*)d_in[6];
    const float* fck_w2  = (const float*)d_in[7];
    const float* fcv_w1  = (const float*)d_in[8];
    const float* fcv_w2  = (const float*)d_in[9];
    const float* wdot_s  = (const float*)d_in[10];
    const float* wdot_v  = (const float*)d_in[11];
    float* out = (float*)d_out;

    int N = in_sizes[0] / 40;
    int E = in_sizes[1] / 2;

    cudaFuncSetAttribute(k_edges, cudaFuncAttributeMaxDynamicSharedMemorySize, SMEM_BYTES);

    k_nodes<<<(N + 63) / 64, 64>>>(node_ft, wqs, wqv, out, N);
    k_edges<<<148, 512, SMEM_BYTES>>>(node_ft, eidx, edge_sh, edge_sc,
                                      fck_w1, fck_w2, fcv_w1, fcv_w2,
                                      wdot_s, wdot_v, E);
    k_alpha<<<(E + 255) / 256, 256>>>(eidx, E);
    k_scatter<<<((long long)E * 10 + 255) / 256, 256>>>(eidx, out, E);
}